// round 1
// baseline (speedup 1.0000x reference)
#include <cuda_runtime.h>
#include <math.h>

#define BATCH 4
#define C     128
#define H     128
#define W     128
#define P     (H*W)      // 16384
#define O     256
#define MID   32
#define KK    49
#define KWID  392        // K*K*G
#define G     8
#define GC    16
#define EPS   1e-6f
#define PX    64         // pixel tile for k_out

// ---- scratch (device globals; no allocation allowed) ----
__device__ float g_wk[BATCH*KWID*P];   // per-pixel involution kernels
__device__ float g_x1[BATCH*C*P];      // raw involution output (pre-LN)
__device__ float g_mu1[BATCH*P];
__device__ float g_rs1[BATCH*P];
__device__ float g_convT[C*O];         // conv_w transposed to (C,O)
__device__ float g_mapT[C*O];          // map_w transposed to (C,O)

__device__ __forceinline__ float gelu_exact(float v){
    return 0.5f*v*(1.0f + erff(v*0.70710678118654752f));
}

// ---------------------------------------------------------------------------
// K0: transpose the two (O,C) weight matrices to (C,O)
// ---------------------------------------------------------------------------
__global__ void k_transpose(const float* __restrict__ conv_w,
                            const float* __restrict__ map_w){
    int idx = blockIdx.x*256 + threadIdx.x;   // 0..32767
    int o = idx / C;
    int c = idx - o*C;
    g_convT[c*O + o] = conv_w[idx];
    g_mapT [c*O + o] = map_w[idx];
}

// ---------------------------------------------------------------------------
// K1: per-pixel kernel-generation MLP: mid = relu(W1 x + b1); wk = W2 mid + b2
//     2 pixels per thread; all weights staged in dynamic smem (~67KB)
// ---------------------------------------------------------------------------
__global__ void __launch_bounds__(256) k_genw(
    const float* __restrict__ x,
    const float* __restrict__ w1, const float* __restrict__ b1,
    const float* __restrict__ w2, const float* __restrict__ b2)
{
    extern __shared__ float sm1[];
    float* w1t = sm1;              // transposed: [c][m], 128*32 = 4096
    float* w2s = w1t + MID*C;      // [kk][m], 392*32 = 12544
    float* b1s = w2s + KWID*MID;   // 32
    float* b2s = b1s + MID;        // 392
    int tid = threadIdx.x;

    for (int i = tid; i < MID*C; i += 256){
        int m = i >> 7, c = i & 127;          // w1 is (MID,C)
        w1t[c*MID + m] = w1[i];
    }
    for (int i = tid; i < KWID*MID; i += 256) w2s[i] = w2[i];
    if (tid < MID) b1s[tid] = b1[tid];
    for (int i = tid; i < KWID; i += 256) b2s[i] = b2[i];
    __syncthreads();

    int bp0 = blockIdx.x*512 + tid;           // this thread: bp0 and bp0+256
    int b  = bp0 / P;
    int p0 = bp0 - b*P;
    const float* xb = x + (size_t)b*C*P;

    float mid0[MID], mid1[MID];
    #pragma unroll
    for (int m=0;m<MID;m++){ mid0[m]=b1s[m]; mid1[m]=b1s[m]; }

    for (int c=0;c<C;c++){
        float xv0 = xb[c*P + p0];
        float xv1 = xb[c*P + p0 + 256];
        const float* wr = &w1t[c*MID];
        #pragma unroll
        for (int m=0;m<MID;m++){
            float wv = wr[m];
            mid0[m] += wv*xv0;
            mid1[m] += wv*xv1;
        }
    }
    #pragma unroll
    for (int m=0;m<MID;m++){
        mid0[m] = fmaxf(mid0[m],0.f);
        mid1[m] = fmaxf(mid1[m],0.f);
    }

    float* wkb = g_wk + (size_t)b*KWID*P;
    for (int kk=0; kk<KWID; kk++){
        float a0 = b2s[kk], a1 = b2s[kk];
        const float* wr = &w2s[kk*MID];
        #pragma unroll
        for (int m=0;m<MID;m++){
            float wv = wr[m];
            a0 += wv*mid0[m];
            a1 += wv*mid1[m];
        }
        wkb[kk*P + p0]       = a0;
        wkb[kk*P + p0 + 256] = a1;
    }
}

// ---------------------------------------------------------------------------
// K2: involution (7x7, 8 groups of 16 ch) + LN1 statistics
//     block = 32x8 pixel tile, smem halo per channel
// ---------------------------------------------------------------------------
__global__ void __launch_bounds__(256) k_inv(const float* __restrict__ x){
    __shared__ float xs[14*38];              // (8+6) x (32+6) halo
    int tid = threadIdx.x;
    int tx = tid & 31;
    int ty = tid >> 5;
    int w0 = blockIdx.x*32;
    int h0 = blockIdx.y*8;
    int b  = blockIdx.z;
    int p  = (h0+ty)*W + (w0+tx);
    const float* xb  = x + (size_t)b*C*P;
    const float* wkb = g_wk + (size_t)b*KWID*P + p;

    float s1 = 0.f, s2 = 0.f;
    for (int g=0; g<G; g++){
        float wkv[KK];
        #pragma unroll
        for (int idx=0; idx<KK; idx++)
            wkv[idx] = wkb[(g*KK+idx)*P];

        for (int cc=0; cc<GC; cc++){
            int c = g*GC + cc;
            __syncthreads();
            for (int e=tid; e<14*38; e+=256){
                int hh = e/38, ww = e - hh*38;
                int gh = h0 + hh - 3, gw = w0 + ww - 3;
                float v = 0.f;
                if (gh>=0 && gh<H && gw>=0 && gw<W)
                    v = xb[c*P + gh*W + gw];
                xs[e] = v;
            }
            __syncthreads();
            const float* xc = &xs[ty*38 + tx];
            float acc = 0.f;
            #pragma unroll
            for (int i=0;i<7;i++)
                #pragma unroll
                for (int j=0;j<7;j++)
                    acc += wkv[i*7+j] * xc[i*38+j];
            g_x1[((size_t)b*C + c)*P + p] = acc;
            s1 += acc;
            s2 += acc*acc;
        }
    }
    float mu  = s1 * (1.0f/128.0f);
    float var = s2 * (1.0f/128.0f) - mu*mu;
    g_mu1[b*P + p] = mu;
    g_rs1[b*P + p] = rsqrtf(var + EPS);
}

// ---------------------------------------------------------------------------
// K3: dual GEMM (conv_w @ gelu(LN1(x1)); map_w @ x + b) + LN2/LN3 + gelu(add)
//     tile: all 256 outputs x 64 pixels; 8x8 register tiles; ~210KB smem
// ---------------------------------------------------------------------------
__global__ void __launch_bounds__(256) k_out(
    const float* __restrict__ x,
    const float* __restrict__ ln1w, const float* __restrict__ ln1b,
    const float* __restrict__ ln2w, const float* __restrict__ ln2b,
    const float* __restrict__ mapb,
    const float* __restrict__ ln3w, const float* __restrict__ ln3b,
    float* __restrict__ out)
{
    extern __shared__ float sm[];
    float* xAs = sm;                 // gelu(LN1(x1)) tile: [C][PX]   8192
    float* xBs = xAs + C*PX;         // x tile:              [C][PX]   8192
    float* Wt  = xBs + C*PX;         // weight k-chunk: [16][O]        4096
    float* y1s = Wt  + 16*O;         // [O][65]                       16640
    float* yms = y1s + O*65;         // [O][65]                       16640

    __shared__ float mu1s[PX], rs1s[PX];
    __shared__ float muA[PX], rsA[PX], muB[PX], rsB[PX];

    int tid = threadIdx.x;
    int blk = blockIdx.x;            // 0..1023
    int b   = blk >> 8;              // / (P/PX) with P/PX = 256
    int p0  = (blk & 255) * PX;
    const float* xb  = x    + (size_t)b*C*P + p0;
    const float* x1b = g_x1 + (size_t)b*C*P + p0;

    if (tid < PX){
        mu1s[tid] = g_mu1[b*P + p0 + tid];
        rs1s[tid] = g_rs1[b*P + p0 + tid];
    }
    __syncthreads();

    // stage input tiles; apply LN1+GELU to the x1 branch on load
    for (int e = tid; e < C*PX; e += 256){
        int c  = e >> 6;
        int px = e & 63;
        float raw = x1b[c*P + px];
        float v = __ldg(&ln1w[c]) * ((raw - mu1s[px]) * rs1s[px]) + __ldg(&ln1b[c]);
        xAs[e] = gelu_exact(v);
        xBs[e] = xb[c*P + px];
    }
    __syncthreads();

    int oIdx = tid >> 3;   // 0..31 -> o block of 8
    int pIdx = tid & 7;    // 0..7  -> px block of 8
    float acc[8][8];

    // ---- GEMM A: y1 = conv_w @ xA ----
    #pragma unroll
    for (int i=0;i<8;i++)
        #pragma unroll
        for (int j=0;j<8;j++) acc[i][j] = 0.f;

    for (int k0=0; k0<C; k0+=16){
        __syncthreads();
        for (int e=tid; e<16*O; e+=256)
            Wt[e] = g_convT[(k0 + (e>>8))*O + (e & 255)];
        __syncthreads();
        #pragma unroll
        for (int k=0;k<16;k++){
            float xr[8], wr[8];
            #pragma unroll
            for (int j=0;j<8;j++) xr[j] = xAs[(k0+k)*PX + pIdx*8 + j];
            #pragma unroll
            for (int i=0;i<8;i++) wr[i] = Wt[k*O + oIdx*8 + i];
            #pragma unroll
            for (int i=0;i<8;i++)
                #pragma unroll
                for (int j=0;j<8;j++)
                    acc[i][j] += wr[i]*xr[j];
        }
    }
    #pragma unroll
    for (int i=0;i<8;i++)
        #pragma unroll
        for (int j=0;j<8;j++)
            y1s[(oIdx*8+i)*65 + pIdx*8+j] = acc[i][j];

    // ---- GEMM B: ym = map_w @ x + map_b ----
    #pragma unroll
    for (int i=0;i<8;i++)
        #pragma unroll
        for (int j=0;j<8;j++) acc[i][j] = 0.f;

    for (int k0=0; k0<C; k0+=16){
        __syncthreads();
        for (int e=tid; e<16*O; e+=256)
            Wt[e] = g_mapT[(k0 + (e>>8))*O + (e & 255)];
        __syncthreads();
        #pragma unroll
        for (int k=0;k<16;k++){
            float xr[8], wr[8];
            #pragma unroll
            for (int j=0;j<8;j++) xr[j] = xBs[(k0+k)*PX + pIdx*8 + j];
            #pragma unroll
            for (int i=0;i<8;i++) wr[i] = Wt[k*O + oIdx*8 + i];
            #pragma unroll
            for (int i=0;i<8;i++)
                #pragma unroll
                for (int j=0;j<8;j++)
                    acc[i][j] += wr[i]*xr[j];
        }
    }
    #pragma unroll
    for (int i=0;i<8;i++){
        float bb = __ldg(&mapb[oIdx*8+i]);
        #pragma unroll
        for (int j=0;j<8;j++)
            yms[(oIdx*8+i)*65 + pIdx*8+j] = acc[i][j] + bb;
    }
    __syncthreads();

    // ---- per-pixel LayerNorm reductions over O=256 (4 threads/pixel) ----
    float* red = Wt;                 // reuse: 16*64 = 1024 floats
    int px = tid & 63;
    int r  = tid >> 6;               // 0..3
    {
        float a1=0.f,a2=0.f,c1=0.f,c2=0.f;
        #pragma unroll 8
        for (int o=r*64; o<r*64+64; o++){
            float v = y1s[o*65+px]; a1+=v; a2+=v*v;
            float u = yms[o*65+px]; c1+=u; c2+=u*u;
        }
        red[(0*4+r)*64+px]=a1; red[(1*4+r)*64+px]=a2;
        red[(2*4+r)*64+px]=c1; red[(3*4+r)*64+px]=c2;
    }
    __syncthreads();
    if (tid < PX){
        float s1=0.f,s2=0.f,t1=0.f,t2=0.f;
        #pragma unroll
        for (int rr=0; rr<4; rr++){
            s1+=red[(0*4+rr)*64+tid]; s2+=red[(1*4+rr)*64+tid];
            t1+=red[(2*4+rr)*64+tid]; t2+=red[(3*4+rr)*64+tid];
        }
        float mA = s1*(1.f/256.f); float vA = s2*(1.f/256.f) - mA*mA;
        muA[tid]=mA; rsA[tid]=rsqrtf(vA+EPS);
        float mB = t1*(1.f/256.f); float vB = t2*(1.f/256.f) - mB*mB;
        muB[tid]=mB; rsB[tid]=rsqrtf(vB+EPS);
    }
    __syncthreads();

    float* outb = out + (size_t)b*O*P + p0;
    for (int rep=0; rep<64; rep++){
        int o = rep*4 + r;
        float v = (y1s[o*65+px]-muA[px])*rsA[px]*__ldg(&ln2w[o]) + __ldg(&ln2b[o]);
        float u = (yms[o*65+px]-muB[px])*rsB[px]*__ldg(&ln3w[o]) + __ldg(&ln3b[o]);
        outb[o*P + px] = gelu_exact(v+u);
    }
}

// ---------------------------------------------------------------------------
extern "C" void kernel_launch(void* const* d_in, const int* in_sizes, int n_in,
                              void* d_out, int out_size)
{
    const float* x     = (const float*)d_in[0];
    const float* w1    = (const float*)d_in[1];
    const float* b1    = (const float*)d_in[2];
    const float* w2    = (const float*)d_in[3];
    const float* b2    = (const float*)d_in[4];
    const float* ln1w  = (const float*)d_in[5];
    const float* ln1b  = (const float*)d_in[6];
    const float* convw = (const float*)d_in[7];
    const float* ln2w  = (const float*)d_in[8];
    const float* ln2b  = (const float*)d_in[9];
    const float* mapw  = (const float*)d_in[10];
    const float* mapb  = (const float*)d_in[11];
    const float* ln3w  = (const float*)d_in[12];
    const float* ln3b  = (const float*)d_in[13];
    float* out = (float*)d_out;

    const int smem_genw = (MID*C + KWID*MID + MID + KWID) * 4;          // 68256
    const int smem_out  = (C*PX*2 + 16*O + O*65*2) * 4;                 // 215040
    cudaFuncSetAttribute(k_genw, cudaFuncAttributeMaxDynamicSharedMemorySize, smem_genw);
    cudaFuncSetAttribute(k_out,  cudaFuncAttributeMaxDynamicSharedMemorySize, smem_out);

    k_transpose<<<128, 256>>>(convw, mapw);
    k_genw<<<128, 256, smem_genw>>>(x, w1, b1, w2, b2);
    dim3 g2(W/32, H/8, BATCH);
    k_inv<<<g2, 256>>>(x);
    k_out<<<BATCH*(P/PX), 256, smem_out>>>(x, ln1w, ln1b, ln2w, ln2b,
                                           mapb, ln3w, ln3b, out);
}

// round 5
// speedup vs baseline: 1.4031x; 1.4031x over previous
#include <cuda_runtime.h>
#include <cuda_bf16.h>
#include <math.h>
#include <stdint.h>

#define BATCH 4
#define C     128
#define H     128
#define W     128
#define P     (H*W)      // 16384
#define O     256
#define MID   32
#define KK    49
#define KWID  392
#define G     8
#define GC    16
#define EPS   1e-6f

// ---- scratch (device globals) ----
__device__ float g_wk[BATCH*KWID*P];
__device__ float g_x1[BATCH*C*P];
__device__ float g_mu1[BATCH*P];
__device__ float g_rs1[BATCH*P];
__device__ __align__(16) __nv_bfloat16 g_Whi[512*C];  // [conv(256); map(256)] x C
__device__ __align__(16) __nv_bfloat16 g_Wlo[512*C];

__device__ __forceinline__ float gelu_exact(float v){
    return 0.5f*v*(1.0f + erff(v*0.70710678118654752f));
}
__device__ __forceinline__ uint32_t smem_u32(const void* p){
    uint32_t a;
    asm("{ .reg .u64 t; cvta.to.shared.u64 t, %1; cvt.u32.u64 %0, t; }" : "=r"(a) : "l"(p));
    return a;
}
__device__ __forceinline__ void ldm4(uint32_t* r, uint32_t addr){
    asm volatile("ldmatrix.sync.aligned.m8n8.x4.shared.b16 {%0,%1,%2,%3}, [%4];"
        : "=r"(r[0]),"=r"(r[1]),"=r"(r[2]),"=r"(r[3]) : "r"(addr));
}
__device__ __forceinline__ void mma16816(float* d, const uint32_t* a, const uint32_t* b){
    asm volatile("mma.sync.aligned.m16n8k16.row.col.f32.bf16.bf16.f32 "
        "{%0,%1,%2,%3}, {%4,%5,%6,%7}, {%8,%9}, {%0,%1,%2,%3};"
        : "+f"(d[0]),"+f"(d[1]),"+f"(d[2]),"+f"(d[3])
        : "r"(a[0]),"r"(a[1]),"r"(a[2]),"r"(a[3]), "r"(b[0]),"r"(b[1]));
}

// ---------------------------------------------------------------------------
// K0: split both weight matrices into bf16 hi/lo: rows [conv(0..255); map(256..511)]
// ---------------------------------------------------------------------------
__global__ void k_prepw(const float* __restrict__ conv_w,
                        const float* __restrict__ map_w){
    int idx = blockIdx.x*256 + threadIdx.x;       // 0..65535
    int r = idx >> 7, c = idx & 127;
    float w = (r < 256) ? conv_w[r*C + c] : map_w[(r-256)*C + c];
    __nv_bfloat16 hi = __float2bfloat16(w);
    g_Whi[idx] = hi;
    g_Wlo[idx] = __float2bfloat16(w - __bfloat162float(hi));
}

// ---------------------------------------------------------------------------
// K1: per-pixel kernel-generation MLP (unchanged)
// ---------------------------------------------------------------------------
__global__ void __launch_bounds__(256) k_genw(
    const float* __restrict__ x,
    const float* __restrict__ w1, const float* __restrict__ b1,
    const float* __restrict__ w2, const float* __restrict__ b2)
{
    extern __shared__ float sm1[];
    float* w1t = sm1;
    float* w2s = w1t + MID*C;
    float* b1s = w2s + KWID*MID;
    float* b2s = b1s + MID;
    int tid = threadIdx.x;

    for (int i = tid; i < MID*C; i += 256){
        int m = i >> 7, c = i & 127;
        w1t[c*MID + m] = w1[i];
    }
    for (int i = tid; i < KWID*MID; i += 256) w2s[i] = w2[i];
    if (tid < MID) b1s[tid] = b1[tid];
    for (int i = tid; i < KWID; i += 256) b2s[i] = b2[i];
    __syncthreads();

    int bp0 = blockIdx.x*512 + tid;
    int b  = bp0 / P;
    int p0 = bp0 - b*P;
    const float* xb = x + (size_t)b*C*P;

    float mid0[MID], mid1[MID];
    #pragma unroll
    for (int m=0;m<MID;m++){ mid0[m]=b1s[m]; mid1[m]=b1s[m]; }

    for (int c=0;c<C;c++){
        float xv0 = xb[c*P + p0];
        float xv1 = xb[c*P + p0 + 256];
        const float* wr = &w1t[c*MID];
        #pragma unroll
        for (int m=0;m<MID;m++){
            float wv = wr[m];
            mid0[m] += wv*xv0;
            mid1[m] += wv*xv1;
        }
    }
    #pragma unroll
    for (int m=0;m<MID;m++){
        mid0[m] = fmaxf(mid0[m],0.f);
        mid1[m] = fmaxf(mid1[m],0.f);
    }

    float* wkb = g_wk + (size_t)b*KWID*P;
    for (int kk=0; kk<KWID; kk++){
        float a0 = b2s[kk], a1 = b2s[kk];
        const float* wr = &w2s[kk*MID];
        #pragma unroll
        for (int m=0;m<MID;m++){
            float wv = wr[m];
            a0 += wv*mid0[m];
            a1 += wv*mid1[m];
        }
        wkb[kk*P + p0]       = a0;
        wkb[kk*P + p0 + 256] = a1;
    }
}

// ---------------------------------------------------------------------------
// K2: involution + LN1 stats (unchanged)
// ---------------------------------------------------------------------------
__global__ void __launch_bounds__(256) k_inv(const float* __restrict__ x){
    __shared__ float xs[14*38];
    int tid = threadIdx.x;
    int tx = tid & 31;
    int ty = tid >> 5;
    int w0 = blockIdx.x*32;
    int h0 = blockIdx.y*8;
    int b  = blockIdx.z;
    int p  = (h0+ty)*W + (w0+tx);
    const float* xb  = x + (size_t)b*C*P;
    const float* wkb = g_wk + (size_t)b*KWID*P + p;

    float s1 = 0.f, s2 = 0.f;
    for (int g=0; g<G; g++){
        float wkv[KK];
        #pragma unroll
        for (int idx=0; idx<KK; idx++)
            wkv[idx] = wkb[(g*KK+idx)*P];

        for (int cc=0; cc<GC; cc++){
            int c = g*GC + cc;
            __syncthreads();
            for (int e=tid; e<14*38; e+=256){
                int hh = e/38, ww = e - hh*38;
                int gh = h0 + hh - 3, gw = w0 + ww - 3;
                float v = 0.f;
                if (gh>=0 && gh<H && gw>=0 && gw<W)
                    v = xb[c*P + gh*W + gw];
                xs[e] = v;
            }
            __syncthreads();
            const float* xc = &xs[ty*38 + tx];
            float acc = 0.f;
            #pragma unroll
            for (int i=0;i<7;i++)
                #pragma unroll
                for (int j=0;j<7;j++)
                    acc += wkv[i*7+j] * xc[i*38+j];
            g_x1[((size_t)b*C + c)*P + p] = acc;
            s1 += acc;
            s2 += acc*acc;
        }
    }
    float mu  = s1 * (1.0f/128.0f);
    float var = s2 * (1.0f/128.0f) - mu*mu;
    g_mu1[b*P + p] = mu;
    g_rs1[b*P + p] = rsqrtf(var + EPS);
}

// ---------------------------------------------------------------------------
// K3: mma.sync dual GEMM + LN2/LN3 + gelu(add)
//  CTA: 256 thr (8 warps: 4 m-warps x 2 n-warps). Tile: 256 o x 64 px, K=128.
//  bf16 3-term split (Wh*Xh + Wh*Xl + Wl*Xh), fp32 accum.
//  dyn smem: XA hi/lo 32K | XB hi/lo 32K | Wchunk hi/lo 64K | ysA 67.6K = 194K
// ---------------------------------------------------------------------------
#define XA_HI 0u
#define XA_LO 16384u
#define XB_HI 32768u
#define XB_LO 49152u
#define WB_HI 65536u
#define WB_LO 98304u
#define YSA   131072u
#define SMEM_MMA (131072 + 256*66*4)    // 198656

__global__ void __launch_bounds__(256,1) k_out_mma(
    const float* __restrict__ x,
    const float* __restrict__ ln1w, const float* __restrict__ ln1b,
    const float* __restrict__ ln2w, const float* __restrict__ ln2b,
    const float* __restrict__ mapb,
    const float* __restrict__ ln3w, const float* __restrict__ ln3b,
    float* __restrict__ out)
{
    extern __shared__ char dsm[];
    __shared__ float sred[4][2][64];
    __shared__ float muA[64], rsA[64], muB[64], rsB[64];
    __shared__ float sLn2w[256], sLn2b[256], sLn3w[256], sLn3b[256], sMapb[256];
    __shared__ float sLn1w[128], sLn1b[128];
    __shared__ float sMu1[64], sRs1[64];

    int tid = threadIdx.x;
    int l   = tid & 31;
    int wid = tid >> 5;
    int mw  = wid & 3;
    int nw  = wid >> 2;
    int m0  = mw*64;
    int n0  = nw*32;
    int blk = blockIdx.x;
    int b   = blk >> 8;
    int p0  = (blk & 255) * 64;

    const float* xb  = x    + (size_t)b*C*P + p0;
    const float* x1b = g_x1 + (size_t)b*C*P + p0;
    float* ysA = (float*)(dsm + YSA);

    // ---- const staging ----
    sLn2w[tid&255] = ln2w[tid&255];   // tid==0..255 exactly
    sLn2b[tid] = ln2b[tid];
    sLn3w[tid] = ln3w[tid];
    sLn3b[tid] = ln3b[tid];
    sMapb[tid] = mapb[tid];
    if (tid < 128){ sLn1w[tid] = ln1w[tid]; sLn1b[tid] = ln1b[tid]; }
    if (tid < 64){
        sMu1[tid] = g_mu1[b*P + p0 + tid];
        sRs1[tid] = g_rs1[b*P + p0 + tid];
    }
    __syncthreads();

    // ---- stage X tiles (swizzled [px][c], bf16 hi/lo) ----
    for (int e = tid; e < C*64; e += 256){
        int c  = e >> 6;
        int px = e & 63;
        float raw = x1b[c*P + px];
        float v = sLn1w[c] * ((raw - sMu1[px]) * sRs1[px]) + sLn1b[c];
        float av = gelu_exact(v);
        float bv = xb[c*P + px];
        uint32_t off = (uint32_t)px*256u + (uint32_t)(((c>>3) ^ (px&7))*16) + (uint32_t)((c&7)*2);
        __nv_bfloat16 ahi = __float2bfloat16(av);
        __nv_bfloat16 alo = __float2bfloat16(av - __bfloat162float(ahi));
        __nv_bfloat16 bhi = __float2bfloat16(bv);
        __nv_bfloat16 blo = __float2bfloat16(bv - __bfloat162float(bhi));
        *(__nv_bfloat16*)(dsm + XA_HI + off) = ahi;
        *(__nv_bfloat16*)(dsm + XA_LO + off) = alo;
        *(__nv_bfloat16*)(dsm + XB_HI + off) = bhi;
        *(__nv_bfloat16*)(dsm + XB_LO + off) = blo;
    }

    uint32_t base = smem_u32(dsm);
    int a_r = (l&7) + ((l>>3)&1)*8;
    int a_u = l>>4;
    int b_r = (l&7) + ((l>>4)&1)*8;
    int b_u = (l>>3)&1;

    float acc[4][4][4];

    for (int br = 0; br < 2; br++){
        #pragma unroll
        for (int i=0;i<4;i++)
            #pragma unroll
            for (int j=0;j<4;j++)
                #pragma unroll
                for (int k=0;k<4;k++) acc[i][j][k] = 0.f;

        uint32_t xbase = base + (br ? XB_HI : XA_HI);

        for (int chunk = 0; chunk < 2; chunk++){
            __syncthreads();
            // stage W chunk [256 rows][64 c] hi+lo, swizzled
            for (int e = tid; e < 2048; e += 256){
                int r = e >> 3, u = e & 7;
                const __nv_bfloat16* srcH = &g_Whi[(br*256 + r)*C + chunk*64 + u*8];
                const __nv_bfloat16* srcL = &g_Wlo[(br*256 + r)*C + chunk*64 + u*8];
                uint32_t phys = (uint32_t)r*128u + (uint32_t)(((u ^ (r&7)))*16);
                *(int4*)(dsm + WB_HI + phys) = *(const int4*)srcH;
                *(int4*)(dsm + WB_LO + phys) = *(const int4*)srcL;
            }
            __syncthreads();

            #pragma unroll
            for (int ks = 0; ks < 4; ks++){
                uint32_t Ah[4][4], Al[4][4];
                #pragma unroll
                for (int i=0;i<4;i++){
                    int row = m0 + 16*i + a_r;
                    uint32_t phys = (uint32_t)row*128u + (uint32_t)((((ks*2 + a_u) ^ (row&7)))*16);
                    ldm4(Ah[i], base + WB_HI + phys);
                    ldm4(Al[i], base + WB_LO + phys);
                }
                uint32_t Bh[8], Bl[8];
                #pragma unroll
                for (int j2=0;j2<2;j2++){
                    int rowp = n0 + 16*j2 + b_r;
                    int unit = chunk*8 + ks*2 + b_u;
                    uint32_t phys = (uint32_t)rowp*256u + (uint32_t)(((unit ^ (rowp&7)))*16);
                    ldm4(&Bh[j2*4], xbase + phys);
                    ldm4(&Bl[j2*4], xbase + 16384u + phys);
                }
                #pragma unroll
                for (int i=0;i<4;i++)
                    #pragma unroll
                    for (int j=0;j<4;j++){
                        mma16816(acc[i][j], Ah[i], &Bh[j*2]);
                        mma16816(acc[i][j], Ah[i], &Bl[j*2]);
                        mma16816(acc[i][j], Al[i], &Bh[j*2]);
                    }
            }
        }

        if (br == 1){
            // add map bias
            #pragma unroll
            for (int i=0;i<4;i++){
                float blo_ = sMapb[m0 + 16*i + (l>>2)];
                float bhi_ = sMapb[m0 + 16*i + 8 + (l>>2)];
                #pragma unroll
                for (int j=0;j<4;j++){
                    acc[i][j][0] += blo_; acc[i][j][1] += blo_;
                    acc[i][j][2] += bhi_; acc[i][j][3] += bhi_;
                }
            }
        }

        // ---- per-pixel stats over this warp's 64 rows ----
        #pragma unroll
        for (int j=0;j<4;j++){
            float p0v=0.f,p1v=0.f,q0v=0.f,q1v=0.f;
            #pragma unroll
            for (int i=0;i<4;i++){
                float d0=acc[i][j][0], d1=acc[i][j][1], d2=acc[i][j][2], d3=acc[i][j][3];
                p0v += d0+d2; p1v += d1+d3;
                q0v += d0*d0+d2*d2; q1v += d1*d1+d3*d3;
            }
            #pragma unroll
            for (int off=4; off<32; off<<=1){
                p0v += __shfl_xor_sync(0xFFFFFFFF, p0v, off);
                p1v += __shfl_xor_sync(0xFFFFFFFF, p1v, off);
                q0v += __shfl_xor_sync(0xFFFFFFFF, q0v, off);
                q1v += __shfl_xor_sync(0xFFFFFFFF, q1v, off);
            }
            if (l < 4){
                int px = n0 + 8*j + 2*l;
                sred[mw][0][px]   = p0v;
                sred[mw][0][px+1] = p1v;
                sred[mw][1][px]   = q0v;
                sred[mw][1][px+1] = q1v;
            }
        }
        if (br == 0){
            // park branch-A result in smem
            #pragma unroll
            for (int i=0;i<4;i++){
                int row = m0 + 16*i + (l>>2);
                #pragma unroll
                for (int j=0;j<4;j++){
                    int col = n0 + 8*j + 2*(l&3);
                    *(float2*)&ysA[row*66 + col]     = make_float2(acc[i][j][0], acc[i][j][1]);
                    *(float2*)&ysA[(row+8)*66 + col] = make_float2(acc[i][j][2], acc[i][j][3]);
                }
            }
        }
        __syncthreads();
        if (tid < 64){
            float s1 = sred[0][0][tid]+sred[1][0][tid]+sred[2][0][tid]+sred[3][0][tid];
            float s2 = sred[0][1][tid]+sred[1][1][tid]+sred[2][1][tid]+sred[3][1][tid];
            float mu = s1*(1.f/256.f);
            float rs = rsqrtf(s2*(1.f/256.f) - mu*mu + EPS);
            if (br == 0){ muA[tid]=mu; rsA[tid]=rs; }
            else        { muB[tid]=mu; rsB[tid]=rs; }
        }
        __syncthreads();
    }

    // ---- final combine: gelu(LN2(yA) + LN3(yB)) into ysA ----
    #pragma unroll
    for (int i=0;i<4;i++){
        #pragma unroll
        for (int j=0;j<4;j++){
            int col = n0 + 8*j + 2*(l&3);
            #pragma unroll
            for (int hh=0; hh<2; hh++){
                int row = m0 + 16*i + (l>>2) + hh*8;
                float2 ya = *(float2*)&ysA[row*66 + col];
                float w2v = sLn2w[row], b2v = sLn2b[row];
                float w3v = sLn3w[row], b3v = sLn3b[row];
                float yb0 = acc[i][j][hh*2+0], yb1 = acc[i][j][hh*2+1];
                float v0 = (ya.x - muA[col  ])*rsA[col  ]*w2v + b2v;
                float v1 = (ya.y - muA[col+1])*rsA[col+1]*w2v + b2v;
                float u0 = (yb0 - muB[col  ])*rsB[col  ]*w3v + b3v;
                float u1 = (yb1 - muB[col+1])*rsB[col+1]*w3v + b3v;
                *(float2*)&ysA[row*66 + col] =
                    make_float2(gelu_exact(v0+u0), gelu_exact(v1+u1));
            }
        }
    }
    __syncthreads();

    float* outb = out + (size_t)b*O*P + p0;
    for (int e = tid; e < O*64; e += 256){
        int o = e >> 6, px = e & 63;
        outb[o*P + px] = ysA[o*66 + px];
    }
}

// ---------------------------------------------------------------------------
extern "C" void kernel_launch(void* const* d_in, const int* in_sizes, int n_in,
                              void* d_out, int out_size)
{
    const float* x     = (const float*)d_in[0];
    const float* w1    = (const float*)d_in[1];
    const float* b1    = (const float*)d_in[2];
    const float* w2    = (const float*)d_in[3];
    const float* b2    = (const float*)d_in[4];
    const float* ln1w  = (const float*)d_in[5];
    const float* ln1b  = (const float*)d_in[6];
    const float* convw = (const float*)d_in[7];
    const float* ln2w  = (const float*)d_in[8];
    const float* ln2b  = (const float*)d_in[9];
    const float* mapw  = (const float*)d_in[10];
    const float* mapb  = (const float*)d_in[11];
    const float* ln3w  = (const float*)d_in[12];
    const float* ln3b  = (const float*)d_in[13];
    float* out = (float*)d_out;

    const int smem_genw = (MID*C + KWID*MID + MID + KWID) * 4;
    cudaFuncSetAttribute(k_genw,    cudaFuncAttributeMaxDynamicSharedMemorySize, smem_genw);
    cudaFuncSetAttribute(k_out_mma, cudaFuncAttributeMaxDynamicSharedMemorySize, SMEM_MMA);

    k_prepw<<<256, 256>>>(convw, mapw);
    k_genw<<<128, 256, smem_genw>>>(x, w1, b1, w2, b2);
    dim3 g2(W/32, H/8, BATCH);
    k_inv<<<g2, 256>>>(x);
    k_out_mma<<<BATCH*(P/64), 256, SMEM_MMA>>>(x, ln1w, ln1b, ln2w, ln2b,
                                               mapb, ln3w, ln3b, out);
}

// round 6
// speedup vs baseline: 2.0818x; 1.4837x over previous
#include <cuda_runtime.h>
#include <cuda_bf16.h>
#include <math.h>
#include <stdint.h>

#define BATCH 4
#define C     128
#define H     128
#define W     128
#define P     (H*W)      // 16384
#define O     256
#define MID   32
#define KK    49
#define KWID  392
#define G     8
#define GC    16
#define EPS   1e-6f

// ---- scratch (device globals) ----
__device__ float g_x1[BATCH*C*P];
__device__ float g_mu1[BATCH*P];
__device__ float g_rs1[BATCH*P];
__device__ __align__(16) __nv_bfloat16 g_Whi[512*C];  // [conv(256); map(256)] x C
__device__ __align__(16) __nv_bfloat16 g_Wlo[512*C];

__device__ __forceinline__ float gelu_exact(float v){
    return 0.5f*v*(1.0f + erff(v*0.70710678118654752f));
}
__device__ __forceinline__ uint32_t smem_u32(const void* p){
    uint32_t a;
    asm("{ .reg .u64 t; cvta.to.shared.u64 t, %1; cvt.u32.u64 %0, t; }" : "=r"(a) : "l"(p));
    return a;
}
__device__ __forceinline__ void ldm4(uint32_t* r, uint32_t addr){
    asm volatile("ldmatrix.sync.aligned.m8n8.x4.shared.b16 {%0,%1,%2,%3}, [%4];"
        : "=r"(r[0]),"=r"(r[1]),"=r"(r[2]),"=r"(r[3]) : "r"(addr));
}
__device__ __forceinline__ void mma16816(float* d, const uint32_t* a, const uint32_t* b){
    asm volatile("mma.sync.aligned.m16n8k16.row.col.f32.bf16.bf16.f32 "
        "{%0,%1,%2,%3}, {%4,%5,%6,%7}, {%8,%9}, {%0,%1,%2,%3};"
        : "+f"(d[0]),"+f"(d[1]),"+f"(d[2]),"+f"(d[3])
        : "r"(a[0]),"r"(a[1]),"r"(a[2]),"r"(a[3]), "r"(b[0]),"r"(b[1]));
}

// ---------------------------------------------------------------------------
// K0: split both weight matrices into bf16 hi/lo
// ---------------------------------------------------------------------------
__global__ void k_prepw(const float* __restrict__ conv_w,
                        const float* __restrict__ map_w){
    int idx = blockIdx.x*256 + threadIdx.x;
    int r = idx >> 7, c = idx & 127;
    float w = (r < 256) ? conv_w[r*C + c] : map_w[(r-256)*C + c];
    __nv_bfloat16 hi = __float2bfloat16(w);
    g_Whi[idx] = hi;
    g_Wlo[idx] = __float2bfloat16(w - __bfloat162float(hi));
}

// ---------------------------------------------------------------------------
// K1: FUSED kernel-gen MLP + involution + LN1 stats.
//  CTA = 32x8 pixel tile (256 thr). mid[32] and wkv[49] register-resident.
//  Halo staged 4 channels/round, prefetched into regs before the sync.
//  smem: w1t 16K | w2s 50K | b2s+b1s | xs 4x544 floats  (~77KB) -> 2 CTA/SM
// ---------------------------------------------------------------------------
#define XS_STRIDE 544
__global__ void __launch_bounds__(256,2) k_invgen(
    const float* __restrict__ x,
    const float* __restrict__ w1, const float* __restrict__ b1,
    const float* __restrict__ w2, const float* __restrict__ b2)
{
    extern __shared__ float sm[];
    float* w1t = sm;                     // [c][m] transposed  : 4096
    float* w2s = w1t + MID*C;            // [kk][m]            : 12544
    float* b2s = w2s + KWID*MID;         // 392
    float* b1s = b2s + KWID;             // 32
    float* xs  = b1s + MID;              // 4 * 544

    int tid = threadIdx.x;
    int tx = tid & 31;
    int ty = tid >> 5;
    int w0 = blockIdx.x*32;
    int h0 = blockIdx.y*8;
    int b  = blockIdx.z;
    int p  = (h0+ty)*W + (w0+tx);
    const float* xb = x + (size_t)b*C*P;

    // ---- stage weights ----
    for (int i = tid; i < MID*C; i += 256){
        int m = i >> 7, c = i & 127;          // w1 is (MID, C) row-major
        w1t[c*MID + m] = w1[i];
    }
    for (int i = tid; i < KWID*MID; i += 256) w2s[i] = w2[i];
    for (int i = tid; i < KWID; i += 256) b2s[i] = b2[i];
    if (tid < MID) b1s[tid] = b1[tid];
    __syncthreads();

    // ---- phase 1: mid = relu(W1 x + b1), register-resident ----
    float mid[MID];
    #pragma unroll
    for (int m=0;m<MID;m++) mid[m] = b1s[m];
    for (int c=0;c<C;c++){
        float xv = xb[c*P + p];
        const float* wr = &w1t[c*MID];
        #pragma unroll
        for (int m=0;m<MID;m++) mid[m] += wr[m]*xv;
    }
    #pragma unroll
    for (int m=0;m<MID;m++) mid[m] = fmaxf(mid[m], 0.f);

    // ---- phase 2: per group, compute wkv then involve 16 channels ----
    float s1 = 0.f, s2 = 0.f;
    for (int g=0; g<G; g++){
        float wkv[KK];
        #pragma unroll
        for (int kk=0; kk<KK; kk++){
            float a = b2s[g*KK + kk];
            const float* wr = &w2s[(g*KK + kk)*MID];
            #pragma unroll
            for (int m=0;m<MID;m++) a += wr[m]*mid[m];
            wkv[kk] = a;
        }

        for (int sub=0; sub<4; sub++){
            int cbase = g*GC + sub*4;
            // prefetch 4-channel halo into regs (overlaps prior compute)
            float rr[3][4];
            #pragma unroll
            for (int pos=0; pos<3; pos++){
                int e = tid + pos*256;
                if (e < 14*38){
                    int hh = e/38, ww = e - hh*38;
                    int gh = h0 + hh - 3, gw = w0 + ww - 3;
                    bool ok = (gh>=0 && gh<H && gw>=0 && gw<W);
                    const float* src = xb + gh*W + gw;
                    #pragma unroll
                    for (int ch=0; ch<4; ch++)
                        rr[pos][ch] = ok ? src[(size_t)(cbase+ch)*P] : 0.f;
                }
            }
            __syncthreads();
            #pragma unroll
            for (int pos=0; pos<3; pos++){
                int e = tid + pos*256;
                if (e < 14*38){
                    #pragma unroll
                    for (int ch=0; ch<4; ch++)
                        xs[ch*XS_STRIDE + e] = rr[pos][ch];
                }
            }
            __syncthreads();

            const float* xc0 = xs + 0*XS_STRIDE + ty*38 + tx;
            const float* xc1 = xs + 1*XS_STRIDE + ty*38 + tx;
            const float* xc2 = xs + 2*XS_STRIDE + ty*38 + tx;
            const float* xc3 = xs + 3*XS_STRIDE + ty*38 + tx;
            float a0=0.f, a1=0.f, a2=0.f, a3=0.f;
            #pragma unroll
            for (int i=0;i<7;i++)
                #pragma unroll
                for (int j=0;j<7;j++){
                    float wv = wkv[i*7+j];
                    int o = i*38 + j;
                    a0 += wv*xc0[o];
                    a1 += wv*xc1[o];
                    a2 += wv*xc2[o];
                    a3 += wv*xc3[o];
                }
            float* dst = g_x1 + ((size_t)b*C + cbase)*P + p;
            dst[0*P] = a0; dst[1*P] = a1; dst[2*P] = a2; dst[3*P] = a3;
            s1 += a0+a1+a2+a3;
            s2 += a0*a0+a1*a1+a2*a2+a3*a3;
        }
    }
    float mu  = s1 * (1.0f/128.0f);
    float var = s2 * (1.0f/128.0f) - mu*mu;
    g_mu1[b*P + p] = mu;
    g_rs1[b*P + p] = rsqrtf(var + EPS);
}

// ---------------------------------------------------------------------------
// K3: mma.sync dual GEMM + LN2/LN3 + gelu(add)  (unchanged from R5)
// ---------------------------------------------------------------------------
#define XA_HI 0u
#define XA_LO 16384u
#define XB_HI 32768u
#define XB_LO 49152u
#define WB_HI 65536u
#define WB_LO 98304u
#define YSA   131072u
#define SMEM_MMA (131072 + 256*66*4)    // 198656

__global__ void __launch_bounds__(256,1) k_out_mma(
    const float* __restrict__ x,
    const float* __restrict__ ln1w, const float* __restrict__ ln1b,
    const float* __restrict__ ln2w, const float* __restrict__ ln2b,
    const float* __restrict__ mapb,
    const float* __restrict__ ln3w, const float* __restrict__ ln3b,
    float* __restrict__ out)
{
    extern __shared__ char dsm[];
    __shared__ float sred[4][2][64];
    __shared__ float muA[64], rsA[64], muB[64], rsB[64];
    __shared__ float sLn2w[256], sLn2b[256], sLn3w[256], sLn3b[256], sMapb[256];
    __shared__ float sLn1w[128], sLn1b[128];
    __shared__ float sMu1[64], sRs1[64];

    int tid = threadIdx.x;
    int l   = tid & 31;
    int wid = tid >> 5;
    int mw  = wid & 3;
    int nw  = wid >> 2;
    int m0  = mw*64;
    int n0  = nw*32;
    int blk = blockIdx.x;
    int b   = blk >> 8;
    int p0  = (blk & 255) * 64;

    const float* xb  = x    + (size_t)b*C*P + p0;
    const float* x1b = g_x1 + (size_t)b*C*P + p0;
    float* ysA = (float*)(dsm + YSA);

    sLn2w[tid] = ln2w[tid];
    sLn2b[tid] = ln2b[tid];
    sLn3w[tid] = ln3w[tid];
    sLn3b[tid] = ln3b[tid];
    sMapb[tid] = mapb[tid];
    if (tid < 128){ sLn1w[tid] = ln1w[tid]; sLn1b[tid] = ln1b[tid]; }
    if (tid < 64){
        sMu1[tid] = g_mu1[b*P + p0 + tid];
        sRs1[tid] = g_rs1[b*P + p0 + tid];
    }
    __syncthreads();

    for (int e = tid; e < C*64; e += 256){
        int c  = e >> 6;
        int px = e & 63;
        float raw = x1b[c*P + px];
        float v = sLn1w[c] * ((raw - sMu1[px]) * sRs1[px]) + sLn1b[c];
        float av = gelu_exact(v);
        float bv = xb[c*P + px];
        uint32_t off = (uint32_t)px*256u + (uint32_t)(((c>>3) ^ (px&7))*16) + (uint32_t)((c&7)*2);
        __nv_bfloat16 ahi = __float2bfloat16(av);
        __nv_bfloat16 alo = __float2bfloat16(av - __bfloat162float(ahi));
        __nv_bfloat16 bhi = __float2bfloat16(bv);
        __nv_bfloat16 blo = __float2bfloat16(bv - __bfloat162float(bhi));
        *(__nv_bfloat16*)(dsm + XA_HI + off) = ahi;
        *(__nv_bfloat16*)(dsm + XA_LO + off) = alo;
        *(__nv_bfloat16*)(dsm + XB_HI + off) = bhi;
        *(__nv_bfloat16*)(dsm + XB_LO + off) = blo;
    }

    uint32_t base = smem_u32(dsm);
    int a_r = (l&7) + ((l>>3)&1)*8;
    int a_u = l>>4;
    int b_r = (l&7) + ((l>>4)&1)*8;
    int b_u = (l>>3)&1;

    float acc[4][4][4];

    for (int br = 0; br < 2; br++){
        #pragma unroll
        for (int i=0;i<4;i++)
            #pragma unroll
            for (int j=0;j<4;j++)
                #pragma unroll
                for (int k=0;k<4;k++) acc[i][j][k] = 0.f;

        uint32_t xbase = base + (br ? XB_HI : XA_HI);

        for (int chunk = 0; chunk < 2; chunk++){
            __syncthreads();
            for (int e = tid; e < 2048; e += 256){
                int r = e >> 3, u = e & 7;
                const __nv_bfloat16* srcH = &g_Whi[(br*256 + r)*C + chunk*64 + u*8];
                const __nv_bfloat16* srcL = &g_Wlo[(br*256 + r)*C + chunk*64 + u*8];
                uint32_t phys = (uint32_t)r*128u + (uint32_t)(((u ^ (r&7)))*16);
                *(int4*)(dsm + WB_HI + phys) = *(const int4*)srcH;
                *(int4*)(dsm + WB_LO + phys) = *(const int4*)srcL;
            }
            __syncthreads();

            #pragma unroll
            for (int ks = 0; ks < 4; ks++){
                uint32_t Ah[4][4], Al[4][4];
                #pragma unroll
                for (int i=0;i<4;i++){
                    int row = m0 + 16*i + a_r;
                    uint32_t phys = (uint32_t)row*128u + (uint32_t)((((ks*2 + a_u) ^ (row&7)))*16);
                    ldm4(Ah[i], base + WB_HI + phys);
                    ldm4(Al[i], base + WB_LO + phys);
                }
                uint32_t Bh[8], Bl[8];
                #pragma unroll
                for (int j2=0;j2<2;j2++){
                    int rowp = n0 + 16*j2 + b_r;
                    int unit = chunk*8 + ks*2 + b_u;
                    uint32_t phys = (uint32_t)rowp*256u + (uint32_t)(((unit ^ (rowp&7)))*16);
                    ldm4(&Bh[j2*4], xbase + phys);
                    ldm4(&Bl[j2*4], xbase + 16384u + phys);
                }
                #pragma unroll
                for (int i=0;i<4;i++)
                    #pragma unroll
                    for (int j=0;j<4;j++){
                        mma16816(acc[i][j], Ah[i], &Bh[j*2]);
                        mma16816(acc[i][j], Ah[i], &Bl[j*2]);
                        mma16816(acc[i][j], Al[i], &Bh[j*2]);
                    }
            }
        }

        if (br == 1){
            #pragma unroll
            for (int i=0;i<4;i++){
                float blo_ = sMapb[m0 + 16*i + (l>>2)];
                float bhi_ = sMapb[m0 + 16*i + 8 + (l>>2)];
                #pragma unroll
                for (int j=0;j<4;j++){
                    acc[i][j][0] += blo_; acc[i][j][1] += blo_;
                    acc[i][j][2] += bhi_; acc[i][j][3] += bhi_;
                }
            }
        }

        #pragma unroll
        for (int j=0;j<4;j++){
            float p0v=0.f,p1v=0.f,q0v=0.f,q1v=0.f;
            #pragma unroll
            for (int i=0;i<4;i++){
                float d0=acc[i][j][0], d1=acc[i][j][1], d2=acc[i][j][2], d3=acc[i][j][3];
                p0v += d0+d2; p1v += d1+d3;
                q0v += d0*d0+d2*d2; q1v += d1*d1+d3*d3;
            }
            #pragma unroll
            for (int off=4; off<32; off<<=1){
                p0v += __shfl_xor_sync(0xFFFFFFFF, p0v, off);
                p1v += __shfl_xor_sync(0xFFFFFFFF, p1v, off);
                q0v += __shfl_xor_sync(0xFFFFFFFF, q0v, off);
                q1v += __shfl_xor_sync(0xFFFFFFFF, q1v, off);
            }
            if (l < 4){
                int px = n0 + 8*j + 2*l;
                sred[mw][0][px]   = p0v;
                sred[mw][0][px+1] = p1v;
                sred[mw][1][px]   = q0v;
                sred[mw][1][px+1] = q1v;
            }
        }
        if (br == 0){
            #pragma unroll
            for (int i=0;i<4;i++){
                int row = m0 + 16*i + (l>>2);
                #pragma unroll
                for (int j=0;j<4;j++){
                    int col = n0 + 8*j + 2*(l&3);
                    *(float2*)&ysA[row*66 + col]     = make_float2(acc[i][j][0], acc[i][j][1]);
                    *(float2*)&ysA[(row+8)*66 + col] = make_float2(acc[i][j][2], acc[i][j][3]);
                }
            }
        }
        __syncthreads();
        if (tid < 64){
            float s1 = sred[0][0][tid]+sred[1][0][tid]+sred[2][0][tid]+sred[3][0][tid];
            float s2 = sred[0][1][tid]+sred[1][1][tid]+sred[2][1][tid]+sred[3][1][tid];
            float mu = s1*(1.f/256.f);
            float rs = rsqrtf(s2*(1.f/256.f) - mu*mu + EPS);
            if (br == 0){ muA[tid]=mu; rsA[tid]=rs; }
            else        { muB[tid]=mu; rsB[tid]=rs; }
        }
        __syncthreads();
    }

    #pragma unroll
    for (int i=0;i<4;i++){
        #pragma unroll
        for (int j=0;j<4;j++){
            int col = n0 + 8*j + 2*(l&3);
            #pragma unroll
            for (int hh=0; hh<2; hh++){
                int row = m0 + 16*i + (l>>2) + hh*8;
                float2 ya = *(float2*)&ysA[row*66 + col];
                float w2v = sLn2w[row], b2v = sLn2b[row];
                float w3v = sLn3w[row], b3v = sLn3b[row];
                float yb0 = acc[i][j][hh*2+0], yb1 = acc[i][j][hh*2+1];
                float v0 = (ya.x - muA[col  ])*rsA[col  ]*w2v + b2v;
                float v1 = (ya.y - muA[col+1])*rsA[col+1]*w2v + b2v;
                float u0 = (yb0 - muB[col  ])*rsB[col  ]*w3v + b3v;
                float u1 = (yb1 - muB[col+1])*rsB[col+1]*w3v + b3v;
                *(float2*)&ysA[row*66 + col] =
                    make_float2(gelu_exact(v0+u0), gelu_exact(v1+u1));
            }
        }
    }
    __syncthreads();

    float* outb = out + (size_t)b*O*P + p0;
    for (int e = tid; e < O*64; e += 256){
        int o = e >> 6, px = e & 63;
        outb[o*P + px] = ysA[o*66 + px];
    }
}

// ---------------------------------------------------------------------------
extern "C" void kernel_launch(void* const* d_in, const int* in_sizes, int n_in,
                              void* d_out, int out_size)
{
    const float* x     = (const float*)d_in[0];
    const float* w1    = (const float*)d_in[1];
    const float* b1    = (const float*)d_in[2];
    const float* w2    = (const float*)d_in[3];
    const float* b2    = (const float*)d_in[4];
    const float* ln1w  = (const float*)d_in[5];
    const float* ln1b  = (const float*)d_in[6];
    const float* convw = (const float*)d_in[7];
    const float* ln2w  = (const float*)d_in[8];
    const float* ln2b  = (const float*)d_in[9];
    const float* mapw  = (const float*)d_in[10];
    const float* mapb  = (const float*)d_in[11];
    const float* ln3w  = (const float*)d_in[12];
    const float* ln3b  = (const float*)d_in[13];
    float* out = (float*)d_out;

    const int smem_invgen = (MID*C + KWID*MID + KWID + MID + 4*XS_STRIDE) * 4;
    cudaFuncSetAttribute(k_invgen,  cudaFuncAttributeMaxDynamicSharedMemorySize, smem_invgen);
    cudaFuncSetAttribute(k_out_mma, cudaFuncAttributeMaxDynamicSharedMemorySize, SMEM_MMA);

    k_prepw<<<256, 256>>>(convw, mapw);
    dim3 g2(W/32, H/8, BATCH);
    k_invgen<<<g2, 256, smem_invgen>>>(x, w1, b1, w2, b2);
    k_out_mma<<<BATCH*(P/64), 256, SMEM_MMA>>>(x, ln1w, ln1b, ln2w, ln2b,
                                               mapb, ln3w, ln3b, out);
}